// round 11
// baseline (speedup 1.0000x reference)
#include <cuda_runtime.h>
#include <cuda_bf16.h>
#include <math.h>

// Problem constants: N=50000, E=800000, D_IN=256, D_OUT=128, H=16
#define NMAX   50000
#define EMAX   800000
#define DOUT   128
#define DIN    256
#define HEDGE  16

#define MTILE  64      // nodes per CTA in proj_mma (2 CTAs/SM)
#define PAW    132     // A plane pitch in 32-bit words
#define P_B    24      // B chunk pitch in bf16

// Scratch (device globals: allocation-free per harness rules)
__device__ float g_xp[NMAX * DOUT];            // x_proj, 25.6 MB (L2-resident)
__device__ float g_s[NMAX];                    // per-node gate
__device__ __nv_bfloat16 g_Wt_hi[DOUT * DIN];  // W_in^T hi plane [n][k]
__device__ __nv_bfloat16 g_Wt_lo[DOUT * DIN];  // W_in^T lo plane [n][k]
// CSR (dst-sorted edges)
__device__ int   g_cnt[NMAX];
__device__ int   g_off[NMAX + 1];
__device__ int   g_cur[NMAX];
__device__ int   g_csr_src[EMAX];
__device__ float g_csr_ew[EMAX];
__device__ int   g_bsum[64];

// ---------------------------------------------------------------------------
__device__ __forceinline__ void split2(float f0, float f1, unsigned& hi, unsigned& lo) {
    asm("cvt.rn.bf16x2.f32 %0, %1, %2;" : "=r"(hi) : "f"(f1), "f"(f0));
    float h0 = __uint_as_float(hi << 16);
    float h1 = __uint_as_float(hi & 0xffff0000u);
    float r0 = f0 - h0;                   // exact (Sterbenz)
    float r1 = f1 - h1;
    asm("cvt.rn.bf16x2.f32 %0, %1, %2;" : "=r"(lo) : "f"(r1), "f"(r0));
}

__device__ __forceinline__ void mma_bf16(float c[4], const unsigned a[4],
                                         unsigned b0, unsigned b1) {
    asm("mma.sync.aligned.m16n8k16.row.col.f32.bf16.bf16.f32 "
        "{%0,%1,%2,%3}, {%4,%5,%6,%7}, {%8,%9}, {%0,%1,%2,%3};"
        : "+f"(c[0]), "+f"(c[1]), "+f"(c[2]), "+f"(c[3])
        : "r"(a[0]), "r"(a[1]), "r"(a[2]), "r"(a[3]), "r"(b0), "r"(b1));
}

// ---------------------------------------------------------------------------
// SMEM layout (bytes) for proj, MTILE = 64
// ---------------------------------------------------------------------------
#define SM_AHI   0                         // 64 x PAW words = 33792 B
#define SM_ALO   33792
#define SM_B0H   67584                     // each B buf: 128 rows x 48 B = 6144
#define SM_B0L   73728
#define SM_B1H   79872
#define SM_B1L   86016
#define SM_W1    92160                     // 128x16 fp32 = 8192 B
#define SM_W2    100352
#define SM_B1V   100416
#define SM_BIN   100480                    // 512 B
#define SM_TOTAL 100992

// ---------------------------------------------------------------------------
// K0: prep — split/transpose W_in to bf16 planes, zero CSR counters
// ---------------------------------------------------------------------------
__global__ void prep_kernel(const float* __restrict__ Win, int n) {
    int i = blockIdx.x * blockDim.x + threadIdx.x;
    int stride = gridDim.x * blockDim.x;
    for (int j = i; j < n; j += stride) g_cnt[j] = 0;
    for (int j = i; j < DIN * DOUT; j += stride) {
        int k  = j >> 7;
        int nn = j & 127;
        float w = Win[j];
        __nv_bfloat16 h = __float2bfloat16_rn(w);
        __nv_bfloat16 l = __float2bfloat16_rn(w - __bfloat162float(h));
        g_Wt_hi[nn * DIN + k] = h;
        g_Wt_lo[nn * DIN + k] = l;
    }
}

__global__ void hist_kernel(const int* __restrict__ ei, int E, int n) {
    int e = blockIdx.x * blockDim.x + threadIdx.x;
    if (e >= E) return;
    int dst = ei[(size_t)E + e];
    if ((unsigned)dst < (unsigned)n) atomicAdd(&g_cnt[dst], 1);
}

// ---------------------------------------------------------------------------
// scan phase 1: per-1024-block exclusive scan + block sums
// ---------------------------------------------------------------------------
__global__ void scan1_kernel(int n) {       // blockDim = 1024
    __shared__ int s[1024];
    int i = blockIdx.x * 1024 + threadIdx.x;
    int v = (i < n) ? g_cnt[i] : 0;
    s[threadIdx.x] = v;
    __syncthreads();
#pragma unroll
    for (int d = 1; d < 1024; d <<= 1) {
        int t = (threadIdx.x >= d) ? s[threadIdx.x - d] : 0;
        __syncthreads();
        s[threadIdx.x] += t;
        __syncthreads();
    }
    if (i < n) g_off[i] = s[threadIdx.x] - v;          // exclusive within block
    if (threadIdx.x == 1023) g_bsum[blockIdx.x] = s[1023];
}

// ---------------------------------------------------------------------------
// scan phase 2+3 fused: each block scans the <=64 block sums inline (cheap),
// then applies the global offset. Eliminates the 4.7us scan2 launch.
// ---------------------------------------------------------------------------
__global__ void scan3_kernel(int n, int nblk) {
    __shared__ int sv[64], sc[64];
    int t = threadIdx.x;
    if (t < 64) {
        int v = (t < nblk) ? g_bsum[t] : 0;
        sv[t] = v;
        sc[t] = v;
    }
    __syncthreads();
#pragma unroll
    for (int d = 1; d < 64; d <<= 1) {
        int tmp = (t < 64 && t >= d) ? sc[t - d] : 0;
        __syncthreads();
        if (t < 64) sc[t] += tmp;
        __syncthreads();
    }
    int i = blockIdx.x * blockDim.x + t;
    if (i >= n) return;
    int b = i >> 10;
    int o = g_off[i] + (sc[b] - sv[b]);                // + exclusive block offset
    g_off[i] = o;
    g_cur[i] = o;
    if (i == n - 1) g_off[n] = o + g_cnt[i];
}

// ---------------------------------------------------------------------------
// scatter: materialize dst-sorted (src, ew) records
// ---------------------------------------------------------------------------
__global__ void scatter_kernel(const int* __restrict__ ei,
                               const float* __restrict__ ew,
                               int E, int n) {
    int e = blockIdx.x * blockDim.x + threadIdx.x;
    if (e >= E) return;
    int dst = ei[(size_t)E + e];
    if ((unsigned)dst >= (unsigned)n) return;
    int src = ei[e];
    int pos = atomicAdd(&g_cur[dst], 1);
    g_csr_src[pos] = ((unsigned)src < (unsigned)n) ? src : -1;
    g_csr_ew[pos]  = ew[e];
}

// ---------------------------------------------------------------------------
// K1: proj via bf16 mma.sync (3-term split) + fused gate MLP.
// MTILE=64, 256 threads = 8 warps (rowgrp 0..3 x colhalf 0..1), 2 CTAs/SM.
// ---------------------------------------------------------------------------
__global__ void __launch_bounds__(256, 2)
proj_mma_kernel(const float* __restrict__ x,
                const float* __restrict__ state,
                const float* __restrict__ bin,
                const float* __restrict__ W1,
                const float* __restrict__ b1,
                const float* __restrict__ W2,
                const float* __restrict__ b2,
                int n) {
    extern __shared__ char smem[];
    unsigned* sAhi = (unsigned*)(smem + SM_AHI);   // [64][PAW] bf16x2 words
    unsigned* sAlo = (unsigned*)(smem + SM_ALO);
    float* sW1 = (float*)(smem + SM_W1);
    float* sW2 = (float*)(smem + SM_W2);
    float* sb1 = (float*)(smem + SM_B1V);
    float* sBN = (float*)(smem + SM_BIN);
    float* sH0 = (float*)(smem + SM_AHI);          // [64][16], aliased post-loop
    float* sH1 = sH0 + MTILE * HEDGE;

    const int tid     = threadIdx.x;
    const int warp    = tid >> 5;
    const int lane    = tid & 31;
    const int gID     = lane >> 2;
    const int tID     = lane & 3;
    const int rowgrp  = warp & 3;
    const int colhalf = warp >> 2;
    const int nb      = blockIdx.x * MTILE;
    const int m0      = rowgrp * 16;
    const int cbase   = colhalf * 64;

    // ---- stage A: split fp32 -> bf16 hi/lo planes, each element ONCE ----
    {
        int r = tid >> 2;          // row 0..63
        int q = tid & 3;           // quarter: 0,1 = x; 2,3 = state
        int gn = nb + r;
        bool valid = (gn < n);
        const float4* src = (q < 2)
            ? (const float4*)(x + (size_t)(valid ? gn : 0) * 128) + (q & 1) * 16
            : (const float4*)(state + (size_t)(valid ? gn : 0) * 128) + (q & 1) * 16;
        unsigned base = r * PAW + q * 32;
#pragma unroll
        for (int j = 0; j < 16; j++) {
            float4 v = valid ? src[j] : make_float4(0.f, 0.f, 0.f, 0.f);
            unsigned h0, l0, h1, l1;
            split2(v.x, v.y, h0, l0);
            split2(v.z, v.w, h1, l1);
            sAhi[base + 2 * j]     = h0;
            sAhi[base + 2 * j + 1] = h1;
            sAlo[base + 2 * j]     = l0;
            sAlo[base + 2 * j + 1] = l1;
        }
    }
    // gate weights + bias
    for (int i = tid; i < DOUT * HEDGE; i += 256) sW1[i] = W1[i];
    if (tid < HEDGE) {
        sW2[tid] = W2[tid];
        sb1[tid] = b1[tid];
    }
    if (tid >= 128) sBN[tid - 128] = bin[tid - 128];

    // ---- B staging: 256 threads = 2 planes x 128 rows, 32 B per row ----
    const int bplane = tid >> 7;          // 0 = hi, 1 = lo
    const int brow   = tid & 127;
    const __nv_bfloat16* gsrc = (bplane ? g_Wt_lo : g_Wt_hi) + brow * DIN;
    char* sBd0 = smem + (bplane ? SM_B0L : SM_B0H) + brow * (P_B * 2);
    char* sBd1 = smem + (bplane ? SM_B1L : SM_B1H) + brow * (P_B * 2);

    // chunk 0 into buf0, prefetch chunk 1
    *(uint4*)(sBd0)      = *(const uint4*)(gsrc);
    *(uint4*)(sBd0 + 16) = *(const uint4*)(gsrc + 8);
    uint4 pf0 = *(const uint4*)(gsrc + 16);
    uint4 pf1 = *(const uint4*)(gsrc + 24);
    __syncthreads();

    float c[8][4];
#pragma unroll
    for (int nt = 0; nt < 8; nt++)
#pragma unroll
        for (int j = 0; j < 4; j++) c[nt][j] = 0.0f;

    for (int kc = 0; kc < 16; kc++) {
        if (kc < 15) {
            char* d = ((kc & 1) == 0) ? sBd1 : sBd0;
            *(uint4*)(d)      = pf0;
            *(uint4*)(d + 16) = pf1;
            if (kc < 14) {
                pf0 = *(const uint4*)(gsrc + (kc + 2) * 16);
                pf1 = *(const uint4*)(gsrc + (kc + 2) * 16 + 8);
            }
        }

        // A fragments: 8 conflict-free LDS.32 (pre-split bf16x2)
        unsigned ah[4], al[4];
        {
            unsigned w0 = (m0 + gID) * PAW + kc * 8 + tID;
            unsigned w1 = w0 + 8 * PAW;
            ah[0] = sAhi[w0];     al[0] = sAlo[w0];
            ah[1] = sAhi[w1];     al[1] = sAlo[w1];
            ah[2] = sAhi[w0 + 4]; al[2] = sAlo[w0 + 4];
            ah[3] = sAhi[w1 + 4]; al[3] = sAlo[w1 + 4];
        }

        const __nv_bfloat16* bH = (const __nv_bfloat16*)
            (smem + ((kc & 1) ? SM_B1H : SM_B0H));
        const __nv_bfloat16* bL = (const __nv_bfloat16*)
            (smem + ((kc & 1) ? SM_B1L : SM_B0L));

#pragma unroll
        for (int nt = 0; nt < 8; nt++) {
            const __nv_bfloat16* ph = bH + (cbase + nt * 8 + gID) * P_B + tID * 2;
            const __nv_bfloat16* pl = bL + (cbase + nt * 8 + gID) * P_B + tID * 2;
            unsigned bh0 = *(const unsigned*)(ph);
            unsigned bh1 = *(const unsigned*)(ph + 8);
            unsigned bl0 = *(const unsigned*)(pl);
            unsigned bl1 = *(const unsigned*)(pl + 8);
            mma_bf16(c[nt], ah, bh0, bh1);
            mma_bf16(c[nt], ah, bl0, bl1);
            mma_bf16(c[nt], al, bh0, bh1);
        }
        __syncthreads();
    }

    // ---- epilogue: + bias, store x_proj, fused gate partials ----
    int r0 = nb + m0 + gID;
    int r1 = r0 + 8;

    float h0a[HEDGE], h1a[HEDGE];
#pragma unroll
    for (int j = 0; j < HEDGE; j++) { h0a[j] = 0.0f; h1a[j] = 0.0f; }

#pragma unroll
    for (int nt = 0; nt < 8; nt++) {
        int col = cbase + nt * 8 + tID * 2;
        float2 bv = make_float2(sBN[col], sBN[col + 1]);
        float o00 = c[nt][0] + bv.x, o01 = c[nt][1] + bv.y;
        float o10 = c[nt][2] + bv.x, o11 = c[nt][3] + bv.y;
        if (r0 < n) *(float2*)(g_xp + (size_t)r0 * 128 + col) = make_float2(o00, o01);
        if (r1 < n) *(float2*)(g_xp + (size_t)r1 * 128 + col) = make_float2(o10, o11);
        const float* w0 = sW1 + col * HEDGE;
        const float* w1 = sW1 + (col + 1) * HEDGE;
#pragma unroll
        for (int j = 0; j < HEDGE; j++) {
            h0a[j] += o00 * w0[j] + o01 * w1[j];
            h1a[j] += o10 * w0[j] + o11 * w1[j];
        }
    }

#pragma unroll
    for (int j = 0; j < HEDGE; j++) {
        h0a[j] += __shfl_xor_sync(0xffffffffu, h0a[j], 1);
        h0a[j] += __shfl_xor_sync(0xffffffffu, h0a[j], 2);
        h1a[j] += __shfl_xor_sync(0xffffffffu, h1a[j], 1);
        h1a[j] += __shfl_xor_sync(0xffffffffu, h1a[j], 2);
    }

    __syncthreads();   // A planes dead -> alias gate partials

    if (tID == 0) {
        float* dst = (colhalf ? sH1 : sH0);
#pragma unroll
        for (int j = 0; j < HEDGE; j++) {
            dst[(m0 + gID) * HEDGE + j]     = h0a[j];
            dst[(m0 + gID + 8) * HEDGE + j] = h1a[j];
        }
    }
    __syncthreads();

    if (tid < MTILE) {
        int gr = nb + tid;
        if (gr < n) {
            float z = b2[0];
#pragma unroll
            for (int j = 0; j < HEDGE; j++) {
                float hv = sH0[tid * HEDGE + j] + sH1[tid * HEDGE + j] + sb1[j];
                hv = hv > 0.0f ? hv : 0.1f * hv;       // leaky_relu(0.1)
                z += hv * sW2[j];
            }
            float wd = 1.0f / (1.0f + expf(-z));
            g_s[gr] = log1pf(expf(4.0f * (wd - 0.5f)));
        }
    }
}

// ---------------------------------------------------------------------------
// K2: pull aggregation + fused finalize. Warp per dst node, atomic-free.
// Unchanged from R10 (proven).
// ---------------------------------------------------------------------------
__global__ void pull_kernel(float* __restrict__ out, int n) {
    int nid  = (blockIdx.x * blockDim.x + threadIdx.x) >> 5;
    int lane = threadIdx.x & 31;
    if (nid >= n) return;

    const int beg = g_off[nid];
    const int end = g_off[nid + 1];

    float4 acc = make_float4(0.f, 0.f, 0.f, 0.f);
    float  sw  = 0.0f;
    const float4* xp4 = (const float4*)g_xp;

    for (int base = beg; base < end; base += 32) {
        int cnt = end - base;
        if (cnt > 32) cnt = 32;

        int   s = 0;
        float w = 0.0f;
        if (lane < cnt) {
            int sv = g_csr_src[base + lane];
            if (sv >= 0) {
                float e = g_csr_ew[base + lane];
                w = e * g_s[sv];
                w = fminf(fmaxf(w, 0.0f), 5.0f);
                s = sv;
            }
        }

#pragma unroll 4
        for (int j = 0; j < cnt; j++) {
            int   sj = __shfl_sync(0xffffffffu, s, j);
            float wj = __shfl_sync(0xffffffffu, w, j);
            float4 v = xp4[(size_t)sj * 32 + lane];
            acc.x += wj * v.x;
            acc.y += wj * v.y;
            acc.z += wj * v.z;
            acc.w += wj * v.w;
            sw += wj;                      // w >= 0 after clip
        }
    }

    float inv = 1.0f / (sw + 1e-6f);
    float4 p  = xp4[(size_t)nid * 32 + lane];
    float v0 = acc.x * inv + p.x;
    float v1 = acc.y * inv + p.y;
    float v2 = acc.z * inv + p.z;
    float v3 = acc.w * inv + p.w;
    const float is2 = 0.70710678118654752f;
    float4 r;
    r.x = 0.5f * v0 * (1.0f + erff(v0 * is2));
    r.y = 0.5f * v1 * (1.0f + erff(v1 * is2));
    r.z = 0.5f * v2 * (1.0f + erff(v2 * is2));
    r.w = 0.5f * v3 * (1.0f + erff(v3 * is2));
    ((float4*)out)[(size_t)nid * 32 + lane] = r;
}

// ---------------------------------------------------------------------------
extern "C" void kernel_launch(void* const* d_in, const int* in_sizes, int n_in,
                              void* d_out, int out_size) {
    const float* x     = (const float*)d_in[0];
    const float* state = (const float*)d_in[1];
    const int*   ei    = (const int*)d_in[2];
    const float* ew    = (const float*)d_in[3];
    const float* Win   = (const float*)d_in[4];
    const float* bin   = (const float*)d_in[5];
    const float* W1    = (const float*)d_in[6];
    const float* b1    = (const float*)d_in[7];
    const float* W2    = (const float*)d_in[8];
    const float* b2    = (const float*)d_in[9];

    int n = in_sizes[0] / 128;     // 50000
    int E = in_sizes[3];           // 800000
    float* out = (float*)d_out;

    static bool attr_set = false;
    if (!attr_set) {
        cudaFuncSetAttribute(proj_mma_kernel,
                             cudaFuncAttributeMaxDynamicSharedMemorySize, SM_TOTAL);
        attr_set = true;
    }

    int nblk = (n + 1023) / 1024;

    prep_kernel<<<512, 256>>>(Win, n);
    hist_kernel<<<(E + 255) / 256, 256>>>(ei, E, n);
    scan1_kernel<<<nblk, 1024>>>(n);
    scan3_kernel<<<(n + 255) / 256, 256>>>(n, nblk);
    scatter_kernel<<<(E + 255) / 256, 256>>>(ei, ew, E, n);

    proj_mma_kernel<<<(n + MTILE - 1) / MTILE, 256, SM_TOTAL>>>(
        x, state, bin, W1, b1, W2, b2, n);

    pull_kernel<<<(n * 32 + 255) / 256, 256>>>(out, n);
}

// round 12
// speedup vs baseline: 1.1264x; 1.1264x over previous
#include <cuda_runtime.h>
#include <cuda_bf16.h>
#include <math.h>

// Problem constants: N=50000, E=800000, D_IN=256, D_OUT=128, H=16
#define NMAX   50000
#define EMAX   800000
#define DOUT   128
#define DIN    256
#define HEDGE  16

#define MTILE  128     // nodes per CTA in proj_mma (R10 proven config)
#define PAW    132     // A plane pitch in 32-bit words
#define P_B    24      // B chunk pitch in bf16

// Scratch (device globals: allocation-free per harness rules)
__device__ float g_xp[NMAX * DOUT];            // x_proj, 25.6 MB (L2-resident)
__device__ float g_s[NMAX];                    // per-node gate
__device__ __nv_bfloat16 g_Wt_hi[DOUT * DIN];  // W_in^T hi plane [n][k]
__device__ __nv_bfloat16 g_Wt_lo[DOUT * DIN];  // W_in^T lo plane [n][k]
// CSR (dst-sorted edges)
__device__ int   g_cnt[NMAX];
__device__ int   g_off[NMAX + 1];
__device__ int   g_cur[NMAX];
__device__ int   g_csr_src[EMAX];
__device__ float g_csr_ew[EMAX];
__device__ int   g_bsum[64];

// ---------------------------------------------------------------------------
__device__ __forceinline__ void split2(float f0, float f1, unsigned& hi, unsigned& lo) {
    asm("cvt.rn.bf16x2.f32 %0, %1, %2;" : "=r"(hi) : "f"(f1), "f"(f0));
    float h0 = __uint_as_float(hi << 16);
    float h1 = __uint_as_float(hi & 0xffff0000u);
    float r0 = f0 - h0;                   // exact (Sterbenz)
    float r1 = f1 - h1;
    asm("cvt.rn.bf16x2.f32 %0, %1, %2;" : "=r"(lo) : "f"(r1), "f"(r0));
}

__device__ __forceinline__ void mma_bf16(float c[4], const unsigned a[4],
                                         unsigned b0, unsigned b1) {
    asm("mma.sync.aligned.m16n8k16.row.col.f32.bf16.bf16.f32 "
        "{%0,%1,%2,%3}, {%4,%5,%6,%7}, {%8,%9}, {%0,%1,%2,%3};"
        : "+f"(c[0]), "+f"(c[1]), "+f"(c[2]), "+f"(c[3])
        : "r"(a[0]), "r"(a[1]), "r"(a[2]), "r"(a[3]), "r"(b0), "r"(b1));
}

// ---------------------------------------------------------------------------
// SMEM layout (bytes) for proj (R10 layout, MTILE = 128)
// ---------------------------------------------------------------------------
#define SM_AHI   0
#define SM_ALO   67584
#define SM_B0H   135168
#define SM_B0L   141312
#define SM_B1H   147456
#define SM_B1L   153600
#define SM_W1    159744
#define SM_W2    167936
#define SM_B1V   168000
#define SM_BIN   168064
#define SM_TOTAL 168576

// ---------------------------------------------------------------------------
// K0: prep — split/transpose W_in to bf16 planes, zero CSR counters
// ---------------------------------------------------------------------------
__global__ void prep_kernel(const float* __restrict__ Win, int n) {
    int i = blockIdx.x * blockDim.x + threadIdx.x;
    int stride = gridDim.x * blockDim.x;
    for (int j = i; j < n; j += stride) g_cnt[j] = 0;
    for (int j = i; j < DIN * DOUT; j += stride) {
        int k  = j >> 7;
        int nn = j & 127;
        float w = Win[j];
        __nv_bfloat16 h = __float2bfloat16_rn(w);
        __nv_bfloat16 l = __float2bfloat16_rn(w - __bfloat162float(h));
        g_Wt_hi[nn * DIN + k] = h;
        g_Wt_lo[nn * DIN + k] = l;
    }
}

__global__ void hist_kernel(const int* __restrict__ ei, int E, int n) {
    int e = blockIdx.x * blockDim.x + threadIdx.x;
    if (e >= E) return;
    int dst = ei[(size_t)E + e];
    if ((unsigned)dst < (unsigned)n) atomicAdd(&g_cnt[dst], 1);
}

// ---------------------------------------------------------------------------
// scan phase 1: per-1024-block exclusive scan + block sums
// ---------------------------------------------------------------------------
__global__ void scan1_kernel(int n) {       // blockDim = 1024
    __shared__ int s[1024];
    int i = blockIdx.x * 1024 + threadIdx.x;
    int v = (i < n) ? g_cnt[i] : 0;
    s[threadIdx.x] = v;
    __syncthreads();
#pragma unroll
    for (int d = 1; d < 1024; d <<= 1) {
        int t = (threadIdx.x >= d) ? s[threadIdx.x - d] : 0;
        __syncthreads();
        s[threadIdx.x] += t;
        __syncthreads();
    }
    if (i < n) g_off[i] = s[threadIdx.x] - v;          // exclusive within block
    if (threadIdx.x == 1023) g_bsum[blockIdx.x] = s[1023];
}

// ---------------------------------------------------------------------------
// scan phase 2+3 fused: each block scans the <=64 block sums inline,
// then applies the global offset (kept from R11: measured fine).
// ---------------------------------------------------------------------------
__global__ void scan3_kernel(int n, int nblk) {
    __shared__ int sv[64], sc[64];
    int t = threadIdx.x;
    if (t < 64) {
        int v = (t < nblk) ? g_bsum[t] : 0;
        sv[t] = v;
        sc[t] = v;
    }
    __syncthreads();
#pragma unroll
    for (int d = 1; d < 64; d <<= 1) {
        int tmp = (t < 64 && t >= d) ? sc[t - d] : 0;
        __syncthreads();
        if (t < 64) sc[t] += tmp;
        __syncthreads();
    }
    int i = blockIdx.x * blockDim.x + t;
    if (i >= n) return;
    int b = i >> 10;
    int o = g_off[i] + (sc[b] - sv[b]);                // + exclusive block offset
    g_off[i] = o;
    g_cur[i] = o;
    if (i == n - 1) g_off[n] = o + g_cnt[i];
}

// ---------------------------------------------------------------------------
// scatter: materialize dst-sorted (src, ew) records
// ---------------------------------------------------------------------------
__global__ void scatter_kernel(const int* __restrict__ ei,
                               const float* __restrict__ ew,
                               int E, int n) {
    int e = blockIdx.x * blockDim.x + threadIdx.x;
    if (e >= E) return;
    int dst = ei[(size_t)E + e];
    if ((unsigned)dst >= (unsigned)n) return;
    int src = ei[e];
    int pos = atomicAdd(&g_cur[dst], 1);
    g_csr_src[pos] = ((unsigned)src < (unsigned)n) ? src : -1;
    g_csr_ew[pos]  = ew[e];
}

// ---------------------------------------------------------------------------
// K1: proj via bf16 mma.sync (3-term split) + fused gate MLP.
// R10 proven config: MTILE=128, 512 threads = 16 warps
// (rowgrp 0..7 x colhalf 0..1), A pre-split once, B double-buffered.
// ---------------------------------------------------------------------------
__global__ void __launch_bounds__(512, 1)
proj_mma_kernel(const float* __restrict__ x,
                const float* __restrict__ state,
                const float* __restrict__ bin,
                const float* __restrict__ W1,
                const float* __restrict__ b1,
                const float* __restrict__ W2,
                const float* __restrict__ b2,
                int n) {
    extern __shared__ char smem[];
    unsigned* sAhi = (unsigned*)(smem + SM_AHI);
    unsigned* sAlo = (unsigned*)(smem + SM_ALO);
    float* sW1 = (float*)(smem + SM_W1);
    float* sW2 = (float*)(smem + SM_W2);
    float* sb1 = (float*)(smem + SM_B1V);
    float* sBN = (float*)(smem + SM_BIN);
    float* sH0 = (float*)(smem + SM_AHI);
    float* sH1 = sH0 + MTILE * HEDGE;

    const int tid     = threadIdx.x;
    const int warp    = tid >> 5;
    const int lane    = tid & 31;
    const int gID     = lane >> 2;
    const int tID     = lane & 3;
    const int rowgrp  = warp & 7;
    const int colhalf = warp >> 3;
    const int nb      = blockIdx.x * MTILE;
    const int m0      = rowgrp * 16;
    const int cbase   = colhalf * 64;

    {
        int r = tid >> 2;
        int q = tid & 3;
        int gn = nb + r;
        bool valid = (gn < n);
        const float4* src = (q < 2)
            ? (const float4*)(x + (size_t)(valid ? gn : 0) * 128) + (q & 1) * 16
            : (const float4*)(state + (size_t)(valid ? gn : 0) * 128) + (q & 1) * 16;
        unsigned base = r * PAW + q * 32;
#pragma unroll
        for (int j = 0; j < 16; j++) {
            float4 v = valid ? src[j] : make_float4(0.f, 0.f, 0.f, 0.f);
            unsigned h0, l0, h1, l1;
            split2(v.x, v.y, h0, l0);
            split2(v.z, v.w, h1, l1);
            sAhi[base + 2 * j]     = h0;
            sAhi[base + 2 * j + 1] = h1;
            sAlo[base + 2 * j]     = l0;
            sAlo[base + 2 * j + 1] = l1;
        }
    }
    for (int i = tid; i < DOUT * HEDGE; i += 512) sW1[i] = W1[i];
    if (tid < HEDGE) {
        sW2[tid] = W2[tid];
        sb1[tid] = b1[tid];
    }
    if (tid >= 512 - DOUT) sBN[tid - (512 - DOUT)] = bin[tid - (512 - DOUT)];

    const int bplane = tid >> 8;
    const int brow   = (tid >> 1) & 127;
    const int bhalf  = tid & 1;
    const __nv_bfloat16* gsrc =
        (bplane ? g_Wt_lo : g_Wt_hi) + brow * DIN + bhalf * 8;
    char* sBd0 = smem + (bplane ? SM_B0L : SM_B0H) + brow * (P_B * 2) + bhalf * 16;
    char* sBd1 = smem + (bplane ? SM_B1L : SM_B1H) + brow * (P_B * 2) + bhalf * 16;

    *(uint4*)sBd0 = *(const uint4*)(gsrc);
    uint4 pf = *(const uint4*)(gsrc + 16);
    __syncthreads();

    float c[8][4];
#pragma unroll
    for (int nt = 0; nt < 8; nt++)
#pragma unroll
        for (int j = 0; j < 4; j++) c[nt][j] = 0.0f;

    for (int kc = 0; kc < 16; kc++) {
        if (kc < 15) {
            *(uint4*)(((kc & 1) == 0) ? sBd1 : sBd0) = pf;
            if (kc < 14) pf = *(const uint4*)(gsrc + (kc + 2) * 16);
        }

        unsigned ah[4], al[4];
        {
            unsigned w0 = (m0 + gID) * PAW + kc * 8 + tID;
            unsigned w1 = w0 + 8 * PAW;
            ah[0] = sAhi[w0];     al[0] = sAlo[w0];
            ah[1] = sAhi[w1];     al[1] = sAlo[w1];
            ah[2] = sAhi[w0 + 4]; al[2] = sAlo[w0 + 4];
            ah[3] = sAhi[w1 + 4]; al[3] = sAlo[w1 + 4];
        }

        const __nv_bfloat16* bH = (const __nv_bfloat16*)
            (smem + ((kc & 1) ? SM_B1H : SM_B0H));
        const __nv_bfloat16* bL = (const __nv_bfloat16*)
            (smem + ((kc & 1) ? SM_B1L : SM_B0L));

#pragma unroll
        for (int nt = 0; nt < 8; nt++) {
            const __nv_bfloat16* ph = bH + (cbase + nt * 8 + gID) * P_B + tID * 2;
            const __nv_bfloat16* pl = bL + (cbase + nt * 8 + gID) * P_B + tID * 2;
            unsigned bh0 = *(const unsigned*)(ph);
            unsigned bh1 = *(const unsigned*)(ph + 8);
            unsigned bl0 = *(const unsigned*)(pl);
            unsigned bl1 = *(const unsigned*)(pl + 8);
            mma_bf16(c[nt], ah, bh0, bh1);
            mma_bf16(c[nt], ah, bl0, bl1);
            mma_bf16(c[nt], al, bh0, bh1);
        }
        __syncthreads();
    }

    int r0 = nb + m0 + gID;
    int r1 = r0 + 8;

    float h0a[HEDGE], h1a[HEDGE];
#pragma unroll
    for (int j = 0; j < HEDGE; j++) { h0a[j] = 0.0f; h1a[j] = 0.0f; }

#pragma unroll
    for (int nt = 0; nt < 8; nt++) {
        int col = cbase + nt * 8 + tID * 2;
        float2 bv = make_float2(sBN[col], sBN[col + 1]);
        float o00 = c[nt][0] + bv.x, o01 = c[nt][1] + bv.y;
        float o10 = c[nt][2] + bv.x, o11 = c[nt][3] + bv.y;
        if (r0 < n) *(float2*)(g_xp + (size_t)r0 * 128 + col) = make_float2(o00, o01);
        if (r1 < n) *(float2*)(g_xp + (size_t)r1 * 128 + col) = make_float2(o10, o11);
        const float* w0 = sW1 + col * HEDGE;
        const float* w1 = sW1 + (col + 1) * HEDGE;
#pragma unroll
        for (int j = 0; j < HEDGE; j++) {
            h0a[j] += o00 * w0[j] + o01 * w1[j];
            h1a[j] += o10 * w0[j] + o11 * w1[j];
        }
    }

#pragma unroll
    for (int j = 0; j < HEDGE; j++) {
        h0a[j] += __shfl_xor_sync(0xffffffffu, h0a[j], 1);
        h0a[j] += __shfl_xor_sync(0xffffffffu, h0a[j], 2);
        h1a[j] += __shfl_xor_sync(0xffffffffu, h1a[j], 1);
        h1a[j] += __shfl_xor_sync(0xffffffffu, h1a[j], 2);
    }

    __syncthreads();

    if (tID == 0) {
        float* dst = (colhalf ? sH1 : sH0);
#pragma unroll
        for (int j = 0; j < HEDGE; j++) {
            dst[(m0 + gID) * HEDGE + j]     = h0a[j];
            dst[(m0 + gID + 8) * HEDGE + j] = h1a[j];
        }
    }
    __syncthreads();

    if (tid < MTILE) {
        int gr = nb + tid;
        if (gr < n) {
            float z = b2[0];
#pragma unroll
            for (int j = 0; j < HEDGE; j++) {
                float hv = sH0[tid * HEDGE + j] + sH1[tid * HEDGE + j] + sb1[j];
                hv = hv > 0.0f ? hv : 0.1f * hv;       // leaky_relu(0.1)
                z += hv * sW2[j];
            }
            float wd = 1.0f / (1.0f + expf(-z));
            g_s[gr] = log1pf(expf(4.0f * (wd - 0.5f)));
        }
    }
}

// ---------------------------------------------------------------------------
// K2: pull aggregation + fused finalize. Warp per dst node, atomic-free.
// Unchanged from R10 (proven).
// ---------------------------------------------------------------------------
__global__ void pull_kernel(float* __restrict__ out, int n) {
    int nid  = (blockIdx.x * blockDim.x + threadIdx.x) >> 5;
    int lane = threadIdx.x & 31;
    if (nid >= n) return;

    const int beg = g_off[nid];
    const int end = g_off[nid + 1];

    float4 acc = make_float4(0.f, 0.f, 0.f, 0.f);
    float  sw  = 0.0f;
    const float4* xp4 = (const float4*)g_xp;

    for (int base = beg; base < end; base += 32) {
        int cnt = end - base;
        if (cnt > 32) cnt = 32;

        int   s = 0;
        float w = 0.0f;
        if (lane < cnt) {
            int sv = g_csr_src[base + lane];
            if (sv >= 0) {
                float e = g_csr_ew[base + lane];
                w = e * g_s[sv];
                w = fminf(fmaxf(w, 0.0f), 5.0f);
                s = sv;
            }
        }

#pragma unroll 4
        for (int j = 0; j < cnt; j++) {
            int   sj = __shfl_sync(0xffffffffu, s, j);
            float wj = __shfl_sync(0xffffffffu, w, j);
            float4 v = xp4[(size_t)sj * 32 + lane];
            acc.x += wj * v.x;
            acc.y += wj * v.y;
            acc.z += wj * v.z;
            acc.w += wj * v.w;
            sw += wj;                      // w >= 0 after clip
        }
    }

    float inv = 1.0f / (sw + 1e-6f);
    float4 p  = xp4[(size_t)nid * 32 + lane];
    float v0 = acc.x * inv + p.x;
    float v1 = acc.y * inv + p.y;
    float v2 = acc.z * inv + p.z;
    float v3 = acc.w * inv + p.w;
    const float is2 = 0.70710678118654752f;
    float4 r;
    r.x = 0.5f * v0 * (1.0f + erff(v0 * is2));
    r.y = 0.5f * v1 * (1.0f + erff(v1 * is2));
    r.z = 0.5f * v2 * (1.0f + erff(v2 * is2));
    r.w = 0.5f * v3 * (1.0f + erff(v3 * is2));
    ((float4*)out)[(size_t)nid * 32 + lane] = r;
}

// ---------------------------------------------------------------------------
extern "C" void kernel_launch(void* const* d_in, const int* in_sizes, int n_in,
                              void* d_out, int out_size) {
    const float* x     = (const float*)d_in[0];
    const float* state = (const float*)d_in[1];
    const int*   ei    = (const int*)d_in[2];
    const float* ew    = (const float*)d_in[3];
    const float* Win   = (const float*)d_in[4];
    const float* bin   = (const float*)d_in[5];
    const float* W1    = (const float*)d_in[6];
    const float* b1    = (const float*)d_in[7];
    const float* W2    = (const float*)d_in[8];
    const float* b2    = (const float*)d_in[9];

    int n = in_sizes[0] / 128;     // 50000
    int E = in_sizes[3];           // 800000
    float* out = (float*)d_out;

    static bool attr_set = false;
    if (!attr_set) {
        cudaFuncSetAttribute(proj_mma_kernel,
                             cudaFuncAttributeMaxDynamicSharedMemorySize, SM_TOTAL);
        attr_set = true;
    }

    int nblk = (n + 1023) / 1024;

    prep_kernel<<<512, 256>>>(Win, n);
    hist_kernel<<<(E + 255) / 256, 256>>>(ei, E, n);
    scan1_kernel<<<nblk, 1024>>>(n);
    scan3_kernel<<<(n + 255) / 256, 256>>>(n, nblk);
    scatter_kernel<<<(E + 255) / 256, 256>>>(ei, ew, E, n);

    proj_mma_kernel<<<(n + MTILE - 1) / MTILE, 512, SM_TOTAL>>>(
        x, state, bin, W1, b1, W2, b2, n);

    pull_kernel<<<(n * 32 + 255) / 256, 256>>>(out, n);
}

// round 13
// speedup vs baseline: 1.2621x; 1.1205x over previous
#include <cuda_runtime.h>
#include <cuda_bf16.h>
#include <math.h>

// Problem constants: N=50000, E=800000, D_IN=256, D_OUT=128, H=16
#define NMAX   50000
#define EMAX   800000
#define DOUT   128
#define DIN    256
#define HEDGE  16

#define MTILE  128     // nodes per CTA in proj_mma (proven config)
#define PAW    132     // A plane pitch in 32-bit words
#define P_B    24      // B chunk pitch in bf16

// Scratch (device globals: allocation-free per harness rules)
__device__ float g_xp[NMAX * DOUT];            // x_proj, 25.6 MB (L2-resident)
__device__ float g_s[NMAX];                    // per-node gate
__device__ __nv_bfloat16 g_Wt_hi[DOUT * DIN];  // W_in^T hi plane [n][k]
__device__ __nv_bfloat16 g_Wt_lo[DOUT * DIN];  // W_in^T lo plane [n][k]
// CSR (dst-sorted edges)
__device__ int   g_cnt[NMAX];
__device__ int   g_off[NMAX + 1];
__device__ int   g_cur[NMAX];
__device__ int2  g_csr[EMAX];                  // (src, ew-bits) per edge
__device__ int   g_bsum[64];

// ---------------------------------------------------------------------------
__device__ __forceinline__ void split2(float f0, float f1, unsigned& hi, unsigned& lo) {
    asm("cvt.rn.bf16x2.f32 %0, %1, %2;" : "=r"(hi) : "f"(f1), "f"(f0));
    float h0 = __uint_as_float(hi << 16);
    float h1 = __uint_as_float(hi & 0xffff0000u);
    float r0 = f0 - h0;                   // exact (Sterbenz)
    float r1 = f1 - h1;
    asm("cvt.rn.bf16x2.f32 %0, %1, %2;" : "=r"(lo) : "f"(r1), "f"(r0));
}

__device__ __forceinline__ void mma_bf16(float c[4], const unsigned a[4],
                                         unsigned b0, unsigned b1) {
    asm("mma.sync.aligned.m16n8k16.row.col.f32.bf16.bf16.f32 "
        "{%0,%1,%2,%3}, {%4,%5,%6,%7}, {%8,%9}, {%0,%1,%2,%3};"
        : "+f"(c[0]), "+f"(c[1]), "+f"(c[2]), "+f"(c[3])
        : "r"(a[0]), "r"(a[1]), "r"(a[2]), "r"(a[3]), "r"(b0), "r"(b1));
}

// ---------------------------------------------------------------------------
// SMEM layout (bytes) for proj (MTILE = 128)
// ---------------------------------------------------------------------------
#define SM_AHI   0
#define SM_ALO   67584
#define SM_B0H   135168
#define SM_B0L   141312
#define SM_B1H   147456
#define SM_B1L   153600
#define SM_W1    159744
#define SM_W2    167936
#define SM_B1V   168000
#define SM_BIN   168064
#define SM_TOTAL 168576

// ---------------------------------------------------------------------------
// side-stream chain: zero counters -> hist -> scan -> scatter
// ---------------------------------------------------------------------------
__global__ void zero_cnt_kernel(int n) {
    int i = blockIdx.x * blockDim.x + threadIdx.x;
    if (i < n) g_cnt[i] = 0;
}

__global__ void hist_kernel(const int* __restrict__ ei, int E, int n) {
    int e = blockIdx.x * blockDim.x + threadIdx.x;
    if (e >= E) return;
    int dst = ei[(size_t)E + e];
    if ((unsigned)dst < (unsigned)n) atomicAdd(&g_cnt[dst], 1);
}

__global__ void scan1_kernel(int n) {       // blockDim = 1024
    __shared__ int s[1024];
    int i = blockIdx.x * 1024 + threadIdx.x;
    int v = (i < n) ? g_cnt[i] : 0;
    s[threadIdx.x] = v;
    __syncthreads();
#pragma unroll
    for (int d = 1; d < 1024; d <<= 1) {
        int t = (threadIdx.x >= d) ? s[threadIdx.x - d] : 0;
        __syncthreads();
        s[threadIdx.x] += t;
        __syncthreads();
    }
    if (i < n) g_off[i] = s[threadIdx.x] - v;          // exclusive within block
    if (threadIdx.x == 1023) g_bsum[blockIdx.x] = s[1023];
}

__global__ void scan3_kernel(int n, int nblk) {
    __shared__ int sv[64], sc[64];
    int t = threadIdx.x;
    if (t < 64) {
        int v = (t < nblk) ? g_bsum[t] : 0;
        sv[t] = v;
        sc[t] = v;
    }
    __syncthreads();
#pragma unroll
    for (int d = 1; d < 64; d <<= 1) {
        int tmp = (t < 64 && t >= d) ? sc[t - d] : 0;
        __syncthreads();
        if (t < 64) sc[t] += tmp;
        __syncthreads();
    }
    int i = blockIdx.x * blockDim.x + t;
    if (i >= n) return;
    int b = i >> 10;
    int o = g_off[i] + (sc[b] - sv[b]);                // + exclusive block offset
    g_off[i] = o;
    g_cur[i] = o;
    if (i == n - 1) g_off[n] = o + g_cnt[i];
}

__global__ void scatter_kernel(const int* __restrict__ ei,
                               const float* __restrict__ ew,
                               int E, int n) {
    int e = blockIdx.x * blockDim.x + threadIdx.x;
    if (e >= E) return;
    int dst = ei[(size_t)E + e];
    if ((unsigned)dst >= (unsigned)n) return;
    int src = ei[e];
    int pos = atomicAdd(&g_cur[dst], 1);
    g_csr[pos] = make_int2(((unsigned)src < (unsigned)n) ? src : -1,
                           __float_as_int(ew[e]));
}

// ---------------------------------------------------------------------------
// main-stream: W-plane prep (split/transpose W_in to bf16 hi/lo)
// ---------------------------------------------------------------------------
__global__ void prepW_kernel(const float* __restrict__ Win) {
    int j = blockIdx.x * blockDim.x + threadIdx.x;
    if (j >= DIN * DOUT) return;
    int k  = j >> 7;
    int nn = j & 127;
    float w = Win[j];
    __nv_bfloat16 h = __float2bfloat16_rn(w);
    __nv_bfloat16 l = __float2bfloat16_rn(w - __bfloat162float(h));
    g_Wt_hi[nn * DIN + k] = h;
    g_Wt_lo[nn * DIN + k] = l;
}

// ---------------------------------------------------------------------------
// K1: proj via bf16 mma.sync (3-term split) + fused gate MLP.
// MTILE=128, 512 threads = 16 warps (rowgrp 0..7 x colhalf 0..1). Unchanged.
// ---------------------------------------------------------------------------
__global__ void __launch_bounds__(512, 1)
proj_mma_kernel(const float* __restrict__ x,
                const float* __restrict__ state,
                const float* __restrict__ bin,
                const float* __restrict__ W1,
                const float* __restrict__ b1,
                const float* __restrict__ W2,
                const float* __restrict__ b2,
                int n) {
    extern __shared__ char smem[];
    unsigned* sAhi = (unsigned*)(smem + SM_AHI);
    unsigned* sAlo = (unsigned*)(smem + SM_ALO);
    float* sW1 = (float*)(smem + SM_W1);
    float* sW2 = (float*)(smem + SM_W2);
    float* sb1 = (float*)(smem + SM_B1V);
    float* sBN = (float*)(smem + SM_BIN);
    float* sH0 = (float*)(smem + SM_AHI);
    float* sH1 = sH0 + MTILE * HEDGE;

    const int tid     = threadIdx.x;
    const int warp    = tid >> 5;
    const int lane    = tid & 31;
    const int gID     = lane >> 2;
    const int tID     = lane & 3;
    const int rowgrp  = warp & 7;
    const int colhalf = warp >> 3;
    const int nb      = blockIdx.x * MTILE;
    const int m0      = rowgrp * 16;
    const int cbase   = colhalf * 64;

    {
        int r = tid >> 2;
        int q = tid & 3;
        int gn = nb + r;
        bool valid = (gn < n);
        const float4* src = (q < 2)
            ? (const float4*)(x + (size_t)(valid ? gn : 0) * 128) + (q & 1) * 16
            : (const float4*)(state + (size_t)(valid ? gn : 0) * 128) + (q & 1) * 16;
        unsigned base = r * PAW + q * 32;
#pragma unroll
        for (int j = 0; j < 16; j++) {
            float4 v = valid ? src[j] : make_float4(0.f, 0.f, 0.f, 0.f);
            unsigned h0, l0, h1, l1;
            split2(v.x, v.y, h0, l0);
            split2(v.z, v.w, h1, l1);
            sAhi[base + 2 * j]     = h0;
            sAhi[base + 2 * j + 1] = h1;
            sAlo[base + 2 * j]     = l0;
            sAlo[base + 2 * j + 1] = l1;
        }
    }
    for (int i = tid; i < DOUT * HEDGE; i += 512) sW1[i] = W1[i];
    if (tid < HEDGE) {
        sW2[tid] = W2[tid];
        sb1[tid] = b1[tid];
    }
    if (tid >= 512 - DOUT) sBN[tid - (512 - DOUT)] = bin[tid - (512 - DOUT)];

    const int bplane = tid >> 8;
    const int brow   = (tid >> 1) & 127;
    const int bhalf  = tid & 1;
    const __nv_bfloat16* gsrc =
        (bplane ? g_Wt_lo : g_Wt_hi) + brow * DIN + bhalf * 8;
    char* sBd0 = smem + (bplane ? SM_B0L : SM_B0H) + brow * (P_B * 2) + bhalf * 16;
    char* sBd1 = smem + (bplane ? SM_B1L : SM_B1H) + brow * (P_B * 2) + bhalf * 16;

    *(uint4*)sBd0 = *(const uint4*)(gsrc);
    uint4 pf = *(const uint4*)(gsrc + 16);
    __syncthreads();

    float c[8][4];
#pragma unroll
    for (int nt = 0; nt < 8; nt++)
#pragma unroll
        for (int j = 0; j < 4; j++) c[nt][j] = 0.0f;

    for (int kc = 0; kc < 16; kc++) {
        if (kc < 15) {
            *(uint4*)(((kc & 1) == 0) ? sBd1 : sBd0) = pf;
            if (kc < 14) pf = *(const uint4*)(gsrc + (kc + 2) * 16);
        }

        unsigned ah[4], al[4];
        {
            unsigned w0 = (m0 + gID) * PAW + kc * 8 + tID;
            unsigned w1 = w0 + 8 * PAW;
            ah[0] = sAhi[w0];     al[0] = sAlo[w0];
            ah[1] = sAhi[w1];     al[1] = sAlo[w1];
            ah[2] = sAhi[w0 + 4]; al[2] = sAlo[w0 + 4];
            ah[3] = sAhi[w1 + 4]; al[3] = sAlo[w1 + 4];
        }

        const __nv_bfloat16* bH = (const __nv_bfloat16*)
            (smem + ((kc & 1) ? SM_B1H : SM_B0H));
        const __nv_bfloat16* bL = (const __nv_bfloat16*)
            (smem + ((kc & 1) ? SM_B1L : SM_B0L));

#pragma unroll
        for (int nt = 0; nt < 8; nt++) {
            const __nv_bfloat16* ph = bH + (cbase + nt * 8 + gID) * P_B + tID * 2;
            const __nv_bfloat16* pl = bL + (cbase + nt * 8 + gID) * P_B + tID * 2;
            unsigned bh0 = *(const unsigned*)(ph);
            unsigned bh1 = *(const unsigned*)(ph + 8);
            unsigned bl0 = *(const unsigned*)(pl);
            unsigned bl1 = *(const unsigned*)(pl + 8);
            mma_bf16(c[nt], ah, bh0, bh1);
            mma_bf16(c[nt], ah, bl0, bl1);
            mma_bf16(c[nt], al, bh0, bh1);
        }
        __syncthreads();
    }

    int r0 = nb + m0 + gID;
    int r1 = r0 + 8;

    float h0a[HEDGE], h1a[HEDGE];
#pragma unroll
    for (int j = 0; j < HEDGE; j++) { h0a[j] = 0.0f; h1a[j] = 0.0f; }

#pragma unroll
    for (int nt = 0; nt < 8; nt++) {
        int col = cbase + nt * 8 + tID * 2;
        float2 bv = make_float2(sBN[col], sBN[col + 1]);
        float o00 = c[nt][0] + bv.x, o01 = c[nt][1] + bv.y;
        float o10 = c[nt][2] + bv.x, o11 = c[nt][3] + bv.y;
        if (r0 < n) *(float2*)(g_xp + (size_t)r0 * 128 + col) = make_float2(o00, o01);
        if (r1 < n) *(float2*)(g_xp + (size_t)r1 * 128 + col) = make_float2(o10, o11);
        const float* w0 = sW1 + col * HEDGE;
        const float* w1 = sW1 + (col + 1) * HEDGE;
#pragma unroll
        for (int j = 0; j < HEDGE; j++) {
            h0a[j] += o00 * w0[j] + o01 * w1[j];
            h1a[j] += o10 * w0[j] + o11 * w1[j];
        }
    }

#pragma unroll
    for (int j = 0; j < HEDGE; j++) {
        h0a[j] += __shfl_xor_sync(0xffffffffu, h0a[j], 1);
        h0a[j] += __shfl_xor_sync(0xffffffffu, h0a[j], 2);
        h1a[j] += __shfl_xor_sync(0xffffffffu, h1a[j], 1);
        h1a[j] += __shfl_xor_sync(0xffffffffu, h1a[j], 2);
    }

    __syncthreads();

    if (tID == 0) {
        float* dst = (colhalf ? sH1 : sH0);
#pragma unroll
        for (int j = 0; j < HEDGE; j++) {
            dst[(m0 + gID) * HEDGE + j]     = h0a[j];
            dst[(m0 + gID + 8) * HEDGE + j] = h1a[j];
        }
    }
    __syncthreads();

    if (tid < MTILE) {
        int gr = nb + tid;
        if (gr < n) {
            float z = b2[0];
#pragma unroll
            for (int j = 0; j < HEDGE; j++) {
                float hv = sH0[tid * HEDGE + j] + sH1[tid * HEDGE + j] + sb1[j];
                hv = hv > 0.0f ? hv : 0.1f * hv;       // leaky_relu(0.1)
                z += hv * sW2[j];
            }
            float wd = 1.0f / (1.0f + expf(-z));
            g_s[gr] = log1pf(expf(4.0f * (wd - 0.5f)));
        }
    }
}

// ---------------------------------------------------------------------------
// K2: pull aggregation + fused finalize. Warp per dst node, atomic-free.
// CSR records now int2 (one 8B load per lane in the resolve phase).
// ---------------------------------------------------------------------------
__global__ void pull_kernel(float* __restrict__ out, int n) {
    int nid  = (blockIdx.x * blockDim.x + threadIdx.x) >> 5;
    int lane = threadIdx.x & 31;
    if (nid >= n) return;

    const int beg = g_off[nid];
    const int end = g_off[nid + 1];

    float4 acc = make_float4(0.f, 0.f, 0.f, 0.f);
    float  sw  = 0.0f;
    const float4* xp4 = (const float4*)g_xp;

    for (int base = beg; base < end; base += 32) {
        int cnt = end - base;
        if (cnt > 32) cnt = 32;

        int   s = 0;
        float w = 0.0f;
        if (lane < cnt) {
            int2 rec = g_csr[base + lane];
            if (rec.x >= 0) {
                float e = __int_as_float(rec.y);
                w = e * g_s[rec.x];
                w = fminf(fmaxf(w, 0.0f), 5.0f);
                s = rec.x;
            }
        }

#pragma unroll 4
        for (int j = 0; j < cnt; j++) {
            int   sj = __shfl_sync(0xffffffffu, s, j);
            float wj = __shfl_sync(0xffffffffu, w, j);
            float4 v = xp4[(size_t)sj * 32 + lane];
            acc.x += wj * v.x;
            acc.y += wj * v.y;
            acc.z += wj * v.z;
            acc.w += wj * v.w;
            sw += wj;                      // w >= 0 after clip
        }
    }

    float inv = 1.0f / (sw + 1e-6f);
    float4 p  = xp4[(size_t)nid * 32 + lane];
    float v0 = acc.x * inv + p.x;
    float v1 = acc.y * inv + p.y;
    float v2 = acc.z * inv + p.z;
    float v3 = acc.w * inv + p.w;
    const float is2 = 0.70710678118654752f;
    float4 r;
    r.x = 0.5f * v0 * (1.0f + erff(v0 * is2));
    r.y = 0.5f * v1 * (1.0f + erff(v1 * is2));
    r.z = 0.5f * v2 * (1.0f + erff(v2 * is2));
    r.w = 0.5f * v3 * (1.0f + erff(v3 * is2));
    ((float4*)out)[(size_t)nid * 32 + lane] = r;
}

// ---------------------------------------------------------------------------
extern "C" void kernel_launch(void* const* d_in, const int* in_sizes, int n_in,
                              void* d_out, int out_size) {
    const float* x     = (const float*)d_in[0];
    const float* state = (const float*)d_in[1];
    const int*   ei    = (const int*)d_in[2];
    const float* ew    = (const float*)d_in[3];
    const float* Win   = (const float*)d_in[4];
    const float* bin   = (const float*)d_in[5];
    const float* W1    = (const float*)d_in[6];
    const float* b1    = (const float*)d_in[7];
    const float* W2    = (const float*)d_in[8];
    const float* b2    = (const float*)d_in[9];

    int n = in_sizes[0] / 128;     // 50000
    int E = in_sizes[3];           // 800000
    float* out = (float*)d_out;

    // one-time host-side resources (created on the uncaptured correctness
    // call; reused identically on every call -> deterministic work)
    static cudaStream_t s2 = 0;
    static cudaEvent_t evF = 0, evJ = 0;
    static bool init_done = false;
    if (!init_done) {
        cudaStreamCreateWithFlags(&s2, cudaStreamNonBlocking);
        cudaEventCreateWithFlags(&evF, cudaEventDisableTiming);
        cudaEventCreateWithFlags(&evJ, cudaEventDisableTiming);
        cudaFuncSetAttribute(proj_mma_kernel,
                             cudaFuncAttributeMaxDynamicSharedMemorySize, SM_TOTAL);
        init_done = true;
    }

    int nblk = (n + 1023) / 1024;

    // fork: CSR build chain on side stream, overlapped with prep_W + proj
    cudaEventRecord(evF, 0);
    cudaStreamWaitEvent(s2, evF, 0);

    zero_cnt_kernel<<<(n + 255) / 256, 256, 0, s2>>>(n);
    hist_kernel<<<(E + 255) / 256, 256, 0, s2>>>(ei, E, n);
    scan1_kernel<<<nblk, 1024, 0, s2>>>(n);
    scan3_kernel<<<(n + 255) / 256, 256, 0, s2>>>(n, nblk);
    scatter_kernel<<<(E + 255) / 256, 256, 0, s2>>>(ei, ew, E, n);
    cudaEventRecord(evJ, s2);

    // main stream: node projection + fused gate
    prepW_kernel<<<(DIN * DOUT + 255) / 256, 256>>>(Win);
    proj_mma_kernel<<<(n + MTILE - 1) / MTILE, 512, SM_TOTAL>>>(
        x, state, bin, W1, b1, W2, b2, n);

    // join, then pull aggregation + fused finalize
    cudaStreamWaitEvent(0, evJ, 0);
    pull_kernel<<<(n * 32 + 255) / 256, 256>>>(out, n);
}

// round 14
// speedup vs baseline: 1.2994x; 1.0296x over previous
#include <cuda_runtime.h>
#include <cuda_bf16.h>
#include <cuda_fp16.h>
#include <math.h>

// Problem constants: N=50000, E=800000, D_IN=256, D_OUT=128, H=16
#define NMAX   50000
#define EMAX   800000
#define DOUT   128
#define DIN    256
#define HEDGE  16

#define MTILE  128     // nodes per CTA in proj_mma (proven config)
#define PAW    132     // A plane pitch in 32-bit words
#define P_B    24      // B chunk pitch in bf16

// Scratch (device globals: allocation-free per harness rules)
__device__ float    g_xp[NMAX * DOUT];         // x_proj fp32 (residual path)
__device__ unsigned g_xph[NMAX * 64];          // x_proj fp16x2 (gather path, 12.8MB)
__device__ float    g_s[NMAX];                 // per-node gate
__device__ __nv_bfloat16 g_Wt_hi[DOUT * DIN];  // W_in^T hi plane [n][k]
__device__ __nv_bfloat16 g_Wt_lo[DOUT * DIN];  // W_in^T lo plane [n][k]
// CSR (dst-sorted edges)
__device__ int   g_cnt[NMAX];
__device__ int   g_off[NMAX + 1];
__device__ int   g_cur[NMAX];
__device__ int2  g_csr[EMAX];                  // (src, ew-bits) per edge
__device__ int   g_bsum[64];

// ---------------------------------------------------------------------------
__device__ __forceinline__ void split2(float f0, float f1, unsigned& hi, unsigned& lo) {
    asm("cvt.rn.bf16x2.f32 %0, %1, %2;" : "=r"(hi) : "f"(f1), "f"(f0));
    float h0 = __uint_as_float(hi << 16);
    float h1 = __uint_as_float(hi & 0xffff0000u);
    float r0 = f0 - h0;                   // exact (Sterbenz)
    float r1 = f1 - h1;
    asm("cvt.rn.bf16x2.f32 %0, %1, %2;" : "=r"(lo) : "f"(r1), "f"(r0));
}

__device__ __forceinline__ void mma_bf16(float c[4], const unsigned a[4],
                                         unsigned b0, unsigned b1) {
    asm("mma.sync.aligned.m16n8k16.row.col.f32.bf16.bf16.f32 "
        "{%0,%1,%2,%3}, {%4,%5,%6,%7}, {%8,%9}, {%0,%1,%2,%3};"
        : "+f"(c[0]), "+f"(c[1]), "+f"(c[2]), "+f"(c[3])
        : "r"(a[0]), "r"(a[1]), "r"(a[2]), "r"(a[3]), "r"(b0), "r"(b1));
}

// ---------------------------------------------------------------------------
// SMEM layout (bytes) for proj (MTILE = 128)
// ---------------------------------------------------------------------------
#define SM_AHI   0
#define SM_ALO   67584
#define SM_B0H   135168
#define SM_B0L   141312
#define SM_B1H   147456
#define SM_B1L   153600
#define SM_W1    159744
#define SM_W2    167936
#define SM_B1V   168000
#define SM_BIN   168064
#define SM_TOTAL 168576

// ---------------------------------------------------------------------------
// side-stream chain: zero counters -> hist -> scan -> scatter
// ---------------------------------------------------------------------------
__global__ void zero_cnt_kernel(int n) {
    int i = blockIdx.x * blockDim.x + threadIdx.x;
    if (i < n) g_cnt[i] = 0;
}

__global__ void hist_kernel(const int* __restrict__ ei, int E, int n) {
    int e = blockIdx.x * blockDim.x + threadIdx.x;
    if (e >= E) return;
    int dst = ei[(size_t)E + e];
    if ((unsigned)dst < (unsigned)n) atomicAdd(&g_cnt[dst], 1);
}

__global__ void scan1_kernel(int n) {       // blockDim = 1024
    __shared__ int s[1024];
    int i = blockIdx.x * 1024 + threadIdx.x;
    int v = (i < n) ? g_cnt[i] : 0;
    s[threadIdx.x] = v;
    __syncthreads();
#pragma unroll
    for (int d = 1; d < 1024; d <<= 1) {
        int t = (threadIdx.x >= d) ? s[threadIdx.x - d] : 0;
        __syncthreads();
        s[threadIdx.x] += t;
        __syncthreads();
    }
    if (i < n) g_off[i] = s[threadIdx.x] - v;          // exclusive within block
    if (threadIdx.x == 1023) g_bsum[blockIdx.x] = s[1023];
}

__global__ void scan3_kernel(int n, int nblk) {
    __shared__ int sv[64], sc[64];
    int t = threadIdx.x;
    if (t < 64) {
        int v = (t < nblk) ? g_bsum[t] : 0;
        sv[t] = v;
        sc[t] = v;
    }
    __syncthreads();
#pragma unroll
    for (int d = 1; d < 64; d <<= 1) {
        int tmp = (t < 64 && t >= d) ? sc[t - d] : 0;
        __syncthreads();
        if (t < 64) sc[t] += tmp;
        __syncthreads();
    }
    int i = blockIdx.x * blockDim.x + t;
    if (i >= n) return;
    int b = i >> 10;
    int o = g_off[i] + (sc[b] - sv[b]);                // + exclusive block offset
    g_off[i] = o;
    g_cur[i] = o;
    if (i == n - 1) g_off[n] = o + g_cnt[i];
}

__global__ void scatter_kernel(const int* __restrict__ ei,
                               const float* __restrict__ ew,
                               int E, int n) {
    int e = blockIdx.x * blockDim.x + threadIdx.x;
    if (e >= E) return;
    int dst = ei[(size_t)E + e];
    if ((unsigned)dst >= (unsigned)n) return;
    int src = ei[e];
    int pos = atomicAdd(&g_cur[dst], 1);
    g_csr[pos] = make_int2(((unsigned)src < (unsigned)n) ? src : -1,
                           __float_as_int(ew[e]));
}

// ---------------------------------------------------------------------------
// main-stream: W-plane prep (split/transpose W_in to bf16 hi/lo)
// ---------------------------------------------------------------------------
__global__ void prepW_kernel(const float* __restrict__ Win) {
    int j = blockIdx.x * blockDim.x + threadIdx.x;
    if (j >= DIN * DOUT) return;
    int k  = j >> 7;
    int nn = j & 127;
    float w = Win[j];
    __nv_bfloat16 h = __float2bfloat16_rn(w);
    __nv_bfloat16 l = __float2bfloat16_rn(w - __bfloat162float(h));
    g_Wt_hi[nn * DIN + k] = h;
    g_Wt_lo[nn * DIN + k] = l;
}

// ---------------------------------------------------------------------------
// K1: proj via bf16 mma.sync (3-term split) + fused gate MLP.
// MTILE=128, 512 threads = 16 warps. Epilogue also writes fp16x2 copy g_xph.
// ---------------------------------------------------------------------------
__global__ void __launch_bounds__(512, 1)
proj_mma_kernel(const float* __restrict__ x,
                const float* __restrict__ state,
                const float* __restrict__ bin,
                const float* __restrict__ W1,
                const float* __restrict__ b1,
                const float* __restrict__ W2,
                const float* __restrict__ b2,
                int n) {
    extern __shared__ char smem[];
    unsigned* sAhi = (unsigned*)(smem + SM_AHI);
    unsigned* sAlo = (unsigned*)(smem + SM_ALO);
    float* sW1 = (float*)(smem + SM_W1);
    float* sW2 = (float*)(smem + SM_W2);
    float* sb1 = (float*)(smem + SM_B1V);
    float* sBN = (float*)(smem + SM_BIN);
    float* sH0 = (float*)(smem + SM_AHI);
    float* sH1 = sH0 + MTILE * HEDGE;

    const int tid     = threadIdx.x;
    const int warp    = tid >> 5;
    const int lane    = tid & 31;
    const int gID     = lane >> 2;
    const int tID     = lane & 3;
    const int rowgrp  = warp & 7;
    const int colhalf = warp >> 3;
    const int nb      = blockIdx.x * MTILE;
    const int m0      = rowgrp * 16;
    const int cbase   = colhalf * 64;

    {
        int r = tid >> 2;
        int q = tid & 3;
        int gn = nb + r;
        bool valid = (gn < n);
        const float4* src = (q < 2)
            ? (const float4*)(x + (size_t)(valid ? gn : 0) * 128) + (q & 1) * 16
            : (const float4*)(state + (size_t)(valid ? gn : 0) * 128) + (q & 1) * 16;
        unsigned base = r * PAW + q * 32;
#pragma unroll
        for (int j = 0; j < 16; j++) {
            float4 v = valid ? src[j] : make_float4(0.f, 0.f, 0.f, 0.f);
            unsigned h0, l0, h1, l1;
            split2(v.x, v.y, h0, l0);
            split2(v.z, v.w, h1, l1);
            sAhi[base + 2 * j]     = h0;
            sAhi[base + 2 * j + 1] = h1;
            sAlo[base + 2 * j]     = l0;
            sAlo[base + 2 * j + 1] = l1;
        }
    }
    for (int i = tid; i < DOUT * HEDGE; i += 512) sW1[i] = W1[i];
    if (tid < HEDGE) {
        sW2[tid] = W2[tid];
        sb1[tid] = b1[tid];
    }
    if (tid >= 512 - DOUT) sBN[tid - (512 - DOUT)] = bin[tid - (512 - DOUT)];

    const int bplane = tid >> 8;
    const int brow   = (tid >> 1) & 127;
    const int bhalf  = tid & 1;
    const __nv_bfloat16* gsrc =
        (bplane ? g_Wt_lo : g_Wt_hi) + brow * DIN + bhalf * 8;
    char* sBd0 = smem + (bplane ? SM_B0L : SM_B0H) + brow * (P_B * 2) + bhalf * 16;
    char* sBd1 = smem + (bplane ? SM_B1L : SM_B1H) + brow * (P_B * 2) + bhalf * 16;

    *(uint4*)sBd0 = *(const uint4*)(gsrc);
    uint4 pf = *(const uint4*)(gsrc + 16);
    __syncthreads();

    float c[8][4];
#pragma unroll
    for (int nt = 0; nt < 8; nt++)
#pragma unroll
        for (int j = 0; j < 4; j++) c[nt][j] = 0.0f;

    for (int kc = 0; kc < 16; kc++) {
        if (kc < 15) {
            *(uint4*)(((kc & 1) == 0) ? sBd1 : sBd0) = pf;
            if (kc < 14) pf = *(const uint4*)(gsrc + (kc + 2) * 16);
        }

        unsigned ah[4], al[4];
        {
            unsigned w0 = (m0 + gID) * PAW + kc * 8 + tID;
            unsigned w1 = w0 + 8 * PAW;
            ah[0] = sAhi[w0];     al[0] = sAlo[w0];
            ah[1] = sAhi[w1];     al[1] = sAlo[w1];
            ah[2] = sAhi[w0 + 4]; al[2] = sAlo[w0 + 4];
            ah[3] = sAhi[w1 + 4]; al[3] = sAlo[w1 + 4];
        }

        const __nv_bfloat16* bH = (const __nv_bfloat16*)
            (smem + ((kc & 1) ? SM_B1H : SM_B0H));
        const __nv_bfloat16* bL = (const __nv_bfloat16*)
            (smem + ((kc & 1) ? SM_B1L : SM_B0L));

#pragma unroll
        for (int nt = 0; nt < 8; nt++) {
            const __nv_bfloat16* ph = bH + (cbase + nt * 8 + gID) * P_B + tID * 2;
            const __nv_bfloat16* pl = bL + (cbase + nt * 8 + gID) * P_B + tID * 2;
            unsigned bh0 = *(const unsigned*)(ph);
            unsigned bh1 = *(const unsigned*)(ph + 8);
            unsigned bl0 = *(const unsigned*)(pl);
            unsigned bl1 = *(const unsigned*)(pl + 8);
            mma_bf16(c[nt], ah, bh0, bh1);
            mma_bf16(c[nt], ah, bl0, bl1);
            mma_bf16(c[nt], al, bh0, bh1);
        }
        __syncthreads();
    }

    int r0 = nb + m0 + gID;
    int r1 = r0 + 8;

    float h0a[HEDGE], h1a[HEDGE];
#pragma unroll
    for (int j = 0; j < HEDGE; j++) { h0a[j] = 0.0f; h1a[j] = 0.0f; }

#pragma unroll
    for (int nt = 0; nt < 8; nt++) {
        int col = cbase + nt * 8 + tID * 2;
        float2 bv = make_float2(sBN[col], sBN[col + 1]);
        float o00 = c[nt][0] + bv.x, o01 = c[nt][1] + bv.y;
        float o10 = c[nt][2] + bv.x, o11 = c[nt][3] + bv.y;
        if (r0 < n) {
            *(float2*)(g_xp + (size_t)r0 * 128 + col) = make_float2(o00, o01);
            __half2 hp = __floats2half2_rn(o00, o01);
            g_xph[(size_t)r0 * 64 + (col >> 1)] = *(unsigned*)&hp;
        }
        if (r1 < n) {
            *(float2*)(g_xp + (size_t)r1 * 128 + col) = make_float2(o10, o11);
            __half2 hp = __floats2half2_rn(o10, o11);
            g_xph[(size_t)r1 * 64 + (col >> 1)] = *(unsigned*)&hp;
        }
        const float* w0 = sW1 + col * HEDGE;
        const float* w1 = sW1 + (col + 1) * HEDGE;
#pragma unroll
        for (int j = 0; j < HEDGE; j++) {
            h0a[j] += o00 * w0[j] + o01 * w1[j];
            h1a[j] += o10 * w0[j] + o11 * w1[j];
        }
    }

#pragma unroll
    for (int j = 0; j < HEDGE; j++) {
        h0a[j] += __shfl_xor_sync(0xffffffffu, h0a[j], 1);
        h0a[j] += __shfl_xor_sync(0xffffffffu, h0a[j], 2);
        h1a[j] += __shfl_xor_sync(0xffffffffu, h1a[j], 1);
        h1a[j] += __shfl_xor_sync(0xffffffffu, h1a[j], 2);
    }

    __syncthreads();

    if (tID == 0) {
        float* dst = (colhalf ? sH1 : sH0);
#pragma unroll
        for (int j = 0; j < HEDGE; j++) {
            dst[(m0 + gID) * HEDGE + j]     = h0a[j];
            dst[(m0 + gID + 8) * HEDGE + j] = h1a[j];
        }
    }
    __syncthreads();

    if (tid < MTILE) {
        int gr = nb + tid;
        if (gr < n) {
            float z = b2[0];
#pragma unroll
            for (int j = 0; j < HEDGE; j++) {
                float hv = sH0[tid * HEDGE + j] + sH1[tid * HEDGE + j] + sb1[j];
                hv = hv > 0.0f ? hv : 0.1f * hv;       // leaky_relu(0.1)
                z += hv * sW2[j];
            }
            float wd = 1.0f / (1.0f + expf(-z));
            g_s[gr] = log1pf(expf(4.0f * (wd - 0.5f)));
        }
    }
}

// ---------------------------------------------------------------------------
// K2: pull aggregation + fused finalize. Warp per dst node, atomic-free.
// Gather now from fp16x2 copy (half the L2 traffic); residual stays fp32.
// ---------------------------------------------------------------------------
__global__ void pull_kernel(float* __restrict__ out, int n) {
    int nid  = (blockIdx.x * blockDim.x + threadIdx.x) >> 5;
    int lane = threadIdx.x & 31;
    if (nid >= n) return;

    const int beg = g_off[nid];
    const int end = g_off[nid + 1];

    float4 acc = make_float4(0.f, 0.f, 0.f, 0.f);
    float  sw  = 0.0f;
    const uint2* xph2 = (const uint2*)g_xph;   // 32 uint2 per row (128 halfs)

    for (int base = beg; base < end; base += 32) {
        int cnt = end - base;
        if (cnt > 32) cnt = 32;

        int   s = 0;
        float w = 0.0f;
        if (lane < cnt) {
            int2 rec = g_csr[base + lane];
            if (rec.x >= 0) {
                float e = __int_as_float(rec.y);
                w = e * g_s[rec.x];
                w = fminf(fmaxf(w, 0.0f), 5.0f);
                s = rec.x;
            }
        }

#pragma unroll 4
        for (int j = 0; j < cnt; j++) {
            int   sj = __shfl_sync(0xffffffffu, s, j);
            float wj = __shfl_sync(0xffffffffu, w, j);
            uint2 hv = xph2[(size_t)sj * 32 + lane];
            float2 f01 = __half22float2(*(__half2*)&hv.x);
            float2 f23 = __half22float2(*(__half2*)&hv.y);
            acc.x += wj * f01.x;
            acc.y += wj * f01.y;
            acc.z += wj * f23.x;
            acc.w += wj * f23.y;
            sw += wj;                      // w >= 0 after clip
        }
    }

    float inv = 1.0f / (sw + 1e-6f);
    float4 p  = ((const float4*)g_xp)[(size_t)nid * 32 + lane];
    float v0 = acc.x * inv + p.x;
    float v1 = acc.y * inv + p.y;
    float v2 = acc.z * inv + p.z;
    float v3 = acc.w * inv + p.w;
    const float is2 = 0.70710678118654752f;
    float4 r;
    r.x = 0.5f * v0 * (1.0f + erff(v0 * is2));
    r.y = 0.5f * v1 * (1.0f + erff(v1 * is2));
    r.z = 0.5f * v2 * (1.0f + erff(v2 * is2));
    r.w = 0.5f * v3 * (1.0f + erff(v3 * is2));
    ((float4*)out)[(size_t)nid * 32 + lane] = r;
}

// ---------------------------------------------------------------------------
extern "C" void kernel_launch(void* const* d_in, const int* in_sizes, int n_in,
                              void* d_out, int out_size) {
    const float* x     = (const float*)d_in[0];
    const float* state = (const float*)d_in[1];
    const int*   ei    = (const int*)d_in[2];
    const float* ew    = (const float*)d_in[3];
    const float* Win   = (const float*)d_in[4];
    const float* bin   = (const float*)d_in[5];
    const float* W1    = (const float*)d_in[6];
    const float* b1    = (const float*)d_in[7];
    const float* W2    = (const float*)d_in[8];
    const float* b2    = (const float*)d_in[9];

    int n = in_sizes[0] / 128;     // 50000
    int E = in_sizes[3];           // 800000
    float* out = (float*)d_out;

    static cudaStream_t s2 = 0;
    static cudaEvent_t evF = 0, evJ = 0;
    static bool init_done = false;
    if (!init_done) {
        cudaStreamCreateWithFlags(&s2, cudaStreamNonBlocking);
        cudaEventCreateWithFlags(&evF, cudaEventDisableTiming);
        cudaEventCreateWithFlags(&evJ, cudaEventDisableTiming);
        cudaFuncSetAttribute(proj_mma_kernel,
                             cudaFuncAttributeMaxDynamicSharedMemorySize, SM_TOTAL);
        init_done = true;
    }

    int nblk = (n + 1023) / 1024;

    // fork: CSR build chain on side stream, overlapped with prep_W + proj
    cudaEventRecord(evF, 0);
    cudaStreamWaitEvent(s2, evF, 0);

    zero_cnt_kernel<<<(n + 255) / 256, 256, 0, s2>>>(n);
    hist_kernel<<<(E + 255) / 256, 256, 0, s2>>>(ei, E, n);
    scan1_kernel<<<nblk, 1024, 0, s2>>>(n);
    scan3_kernel<<<(n + 255) / 256, 256, 0, s2>>>(n, nblk);
    scatter_kernel<<<(E + 255) / 256, 256, 0, s2>>>(ei, ew, E, n);
    cudaEventRecord(evJ, s2);

    // main stream: node projection + fused gate
    prepW_kernel<<<(DIN * DOUT + 255) / 256, 256>>>(Win);
    proj_mma_kernel<<<(n + MTILE - 1) / MTILE, 512, SM_TOTAL>>>(
        x, state, bin, W1, b1, W2, b2, n);

    // join, then pull aggregation + fused finalize
    cudaStreamWaitEvent(0, evJ, 0);
    pull_kernel<<<(n * 32 + 255) / 256, 256>>>(out, n);
}